// round 1
// baseline (speedup 1.0000x reference)
#include <cuda_runtime.h>
#include <cuda_bf16.h>

// Problem constants
#define BATCH 4096
#define SEQ   512
#define HID   32
#define NB    4            // batch elements per warp

// Scratch (device globals are the allowed scratch mechanism)
__device__ float g_W1p[32 * 32 * 4];      // packed Whh1: [k][j] -> float4{Wi,Wf,Wg,Wo}
__device__ float g_hf[HID * BATCH];       // final h of cell1, layout [j][b]
__device__ float g_cf[HID * BATCH];       // final c of cell1, layout [j][b]

// ---- fast, accurate activations (MUFU EX2 + RCP; ~1e-6 abs err) ----
__device__ __forceinline__ float sigf(float v) {
    // 1/(1+exp(-v)); __expf -> EX2-based, __fdividef -> RCP-based
    return __fdividef(1.0f, 1.0f + __expf(-v));
}
__device__ __forceinline__ float tanhf_fast(float v) {
    // tanh(v) = 2/(1+exp(-2v)) - 1 ; saturates correctly at +-1
    return __fdividef(2.0f, 1.0f + __expf(-2.0f * v)) - 1.0f;
}

// ---------------------------------------------------------------------------
// Kernel 0: pack Whh1 [128,32] row-major into [k][j] float4 (i,f,g,o) layout
// ---------------------------------------------------------------------------
__global__ void pack_kernel(const float* __restrict__ Whh1) {
    int idx = blockIdx.x * blockDim.x + threadIdx.x;   // 0..1023
    if (idx < 1024) {
        int k = idx >> 5;
        int j = idx & 31;
        float4 w;
        w.x = Whh1[(0  + j) * HID + k];   // i gate
        w.y = Whh1[(32 + j) * HID + k];   // f gate
        w.z = Whh1[(64 + j) * HID + k];   // g gate
        w.w = Whh1[(96 + j) * HID + k];   // o gate
        reinterpret_cast<float4*>(g_W1p)[idx] = w;     // idx = k*32 + j
    }
}

// ---------------------------------------------------------------------------
// Kernel 1: the sequential scan. 1 warp per block; warp lane = hidden unit j;
// each warp carries NB=4 batch elements' (h,c) in registers across 512 steps.
// ---------------------------------------------------------------------------
__global__ void __launch_bounds__(32) scan_kernel(
    const float* __restrict__ x,
    const float* __restrict__ h0,  const float* __restrict__ c0,
    const float* __restrict__ Wih1,
    const float* __restrict__ bih1, const float* __restrict__ bhh1)
{
    __shared__ float4 Ws[32 * 32];       // 16 KB: [k][j] packed gate weights
    const int j = threadIdx.x;           // lane = hidden unit
    const int b0 = blockIdx.x * NB;

    // Stage packed weights into shared memory (each lane writes/reads its own j column)
    #pragma unroll
    for (int i = 0; i < 32; i++)
        Ws[i * 32 + j] = reinterpret_cast<const float4*>(g_W1p)[i * 32 + j];
    __syncwarp();

    // Per-lane constants: combined bias and input weight for the 4 gates of unit j
    float4 bias, wih;
    bias.x = bih1[0  + j] + bhh1[0  + j];
    bias.y = bih1[32 + j] + bhh1[32 + j];
    bias.z = bih1[64 + j] + bhh1[64 + j];
    bias.w = bih1[96 + j] + bhh1[96 + j];
    wih.x = Wih1[0  + j];
    wih.y = Wih1[32 + j];
    wih.z = Wih1[64 + j];
    wih.w = Wih1[96 + j];

    // Carry state in registers
    float h[NB], c[NB];
    #pragma unroll
    for (int b = 0; b < NB; b++) {
        h[b] = h0[(b0 + b) * HID + j];
        c[b] = c0[(b0 + b) * HID + j];
    }

    // lane b (<NB) holds x[t][b0+b]; prefetch one step ahead
    float xc = (j < NB) ? x[0 * BATCH + b0 + j] : 0.0f;

    #pragma unroll 1
    for (int t = 0; t < SEQ; t++) {
        // prefetch next step's x while this step computes
        float xn = 0.0f;
        if (j < NB && t + 1 < SEQ) xn = x[(t + 1) * BATCH + b0 + j];

        float ai[NB], af[NB], ag[NB], ao[NB];
        #pragma unroll
        for (int b = 0; b < NB; b++) {
            float xb = __shfl_sync(0xffffffffu, xc, b);
            ai[b] = fmaf(xb, wih.x, bias.x);
            af[b] = fmaf(xb, wih.y, bias.y);
            ag[b] = fmaf(xb, wih.z, bias.z);
            ao[b] = fmaf(xb, wih.w, bias.w);
        }

        // recurrent matvec: one LDS.128 per k serves all NB batches
        #pragma unroll
        for (int k = 0; k < 32; k++) {
            float4 w = Ws[k * 32 + j];
            #pragma unroll
            for (int b = 0; b < NB; b++) {
                float hk = __shfl_sync(0xffffffffu, h[b], k);
                ai[b] = fmaf(hk, w.x, ai[b]);
                af[b] = fmaf(hk, w.y, af[b]);
                ag[b] = fmaf(hk, w.z, ag[b]);
                ao[b] = fmaf(hk, w.w, ao[b]);
            }
        }

        #pragma unroll
        for (int b = 0; b < NB; b++) {
            float ig = sigf(ai[b]);
            float fg = sigf(af[b]);
            float gg = tanhf_fast(ag[b]);
            float og = sigf(ao[b]);
            c[b] = fmaf(fg, c[b], ig * gg);
            h[b] = og * tanhf_fast(c[b]);
        }
        xc = xn;
    }

    // write final state, layout [j][b] so the tail kernel reads coalesced
    #pragma unroll
    for (int b = 0; b < NB; b++) {
        g_hf[j * BATCH + b0 + b] = h[b];
        g_cf[j * BATCH + b0 + b] = c[b];
    }
}

// ---------------------------------------------------------------------------
// Kernel 2: cell 2 (input = hidden = hf, cell = cf) + FC. One thread per batch.
// Wih2 + Whh2 folded into a single [128,32] matrix.
// ---------------------------------------------------------------------------
__global__ void __launch_bounds__(128) tail_kernel(
    const float* __restrict__ Wih2, const float* __restrict__ Whh2,
    const float* __restrict__ bih2, const float* __restrict__ bhh2,
    const float* __restrict__ Wfc,  const float* __restrict__ bfc,
    float* __restrict__ out)
{
    __shared__ float W2s[128 * 32];
    __shared__ float b2s[128];
    __shared__ float wfcs[32];
    const int tid = threadIdx.x;

    for (int i = tid; i < 128 * 32; i += 128) W2s[i] = Wih2[i] + Whh2[i];
    if (tid < 128) b2s[tid] = bih2[tid] + bhh2[tid];
    if (tid < 32)  wfcs[tid] = Wfc[tid];
    __syncthreads();

    const int b = blockIdx.x * 128 + tid;

    float h[HID];
    #pragma unroll
    for (int k = 0; k < HID; k++) h[k] = g_hf[k * BATCH + b];   // coalesced

    float acc_out = bfc[0];
    #pragma unroll
    for (int jj = 0; jj < HID; jj++) {
        float ai = b2s[0  + jj];
        float af = b2s[32 + jj];
        float ag = b2s[64 + jj];
        float ao = b2s[96 + jj];
        #pragma unroll
        for (int k = 0; k < HID; k++) {
            float hk = h[k];
            ai = fmaf(hk, W2s[(0  + jj) * HID + k], ai);
            af = fmaf(hk, W2s[(32 + jj) * HID + k], af);
            ag = fmaf(hk, W2s[(64 + jj) * HID + k], ag);
            ao = fmaf(hk, W2s[(96 + jj) * HID + k], ao);
        }
        float cf = g_cf[jj * BATCH + b];
        float cn = fmaf(sigf(af), cf, sigf(ai) * tanhf_fast(ag));
        float hn = sigf(ao) * tanhf_fast(cn);
        acc_out = fmaf(hn, wfcs[jj], acc_out);
    }
    out[b] = acc_out;
}

// ---------------------------------------------------------------------------
// kernel_launch: pack -> scan -> tail (all on default stream, graph-capturable)
// Input order per metadata: x,h0,c0,h1,c1,Wih1,Whh1,bih1,bhh1,Wih2,Whh2,bih2,bhh2,Wfc,bfc
// (h1,c1 are unused by the reference).
// ---------------------------------------------------------------------------
extern "C" void kernel_launch(void* const* d_in, const int* in_sizes, int n_in,
                              void* d_out, int out_size)
{
    const float* x    = (const float*)d_in[0];
    const float* h0   = (const float*)d_in[1];
    const float* c0   = (const float*)d_in[2];
    const float* Wih1 = (const float*)d_in[5];
    const float* Whh1 = (const float*)d_in[6];
    const float* bih1 = (const float*)d_in[7];
    const float* bhh1 = (const float*)d_in[8];
    const float* Wih2 = (const float*)d_in[9];
    const float* Whh2 = (const float*)d_in[10];
    const float* bih2 = (const float*)d_in[11];
    const float* bhh2 = (const float*)d_in[12];
    const float* Wfc  = (const float*)d_in[13];
    const float* bfc  = (const float*)d_in[14];
    float* out = (float*)d_out;

    pack_kernel<<<8, 128>>>(Whh1);
    scan_kernel<<<BATCH / NB, 32>>>(x, h0, c0, Wih1, bih1, bhh1);
    tail_kernel<<<BATCH / 128, 128>>>(Wih2, Whh2, bih2, bhh2, Wfc, bfc, out);
}

// round 2
// speedup vs baseline: 1.0285x; 1.0285x over previous
#include <cuda_runtime.h>
#include <cuda_bf16.h>

// Problem constants
#define BATCH 4096
#define SEQ   512
#define HID   32
#define NB    8            // batch elements per warp

// Scratch (device globals are the allowed scratch mechanism)
__device__ float4 g_W1p[32 * 32];         // packed Whh1: [k][j] -> (Wi,Wf,Wg,Wo)
__device__ float  g_hf[HID * BATCH];      // final h of cell1, layout [j][b]
__device__ float  g_cf[HID * BATCH];      // final c of cell1, layout [j][b]

using u64 = unsigned long long;

// ---- packed f32x2 helpers (Blackwell FFMA2 path, PTX-only) ----
__device__ __forceinline__ u64 pack2(float lo, float hi) {
    u64 r; asm("mov.b64 %0, {%1, %2};" : "=l"(r) : "f"(lo), "f"(hi)); return r;
}
__device__ __forceinline__ void unpack2(u64 v, float& lo, float& hi) {
    asm("mov.b64 {%0, %1}, %2;" : "=f"(lo), "=f"(hi) : "l"(v));
}
__device__ __forceinline__ u64 fma2(u64 a, u64 b, u64 c) {
    u64 d; asm("fma.rn.f32x2 %0, %1, %2, %3;" : "=l"(d) : "l"(a), "l"(b), "l"(c)); return d;
}

// ---- fast, accurate activations (MUFU EX2 + RCP; ~1e-6 abs err) ----
__device__ __forceinline__ float sigf(float v) {
    return __fdividef(1.0f, 1.0f + __expf(-v));
}
__device__ __forceinline__ float tanhf_fast(float v) {
    return __fdividef(2.0f, 1.0f + __expf(-2.0f * v)) - 1.0f;
}

// ---------------------------------------------------------------------------
// Kernel 0: pack Whh1 [128,32] row-major into [k][j] float4 (i,f,g,o) layout
// ---------------------------------------------------------------------------
__global__ void pack_kernel(const float* __restrict__ Whh1) {
    int idx = blockIdx.x * blockDim.x + threadIdx.x;   // 0..1023
    if (idx < 1024) {
        int k = idx >> 5;
        int j = idx & 31;
        float4 w;
        w.x = Whh1[(0  + j) * HID + k];   // i gate
        w.y = Whh1[(32 + j) * HID + k];   // f gate
        w.z = Whh1[(64 + j) * HID + k];   // g gate
        w.w = Whh1[(96 + j) * HID + k];   // o gate
        g_W1p[idx] = w;                   // idx = k*32 + j
    }
}

// ---------------------------------------------------------------------------
// Kernel 1: sequential scan. 1 warp per block; lane = hidden unit j; each
// warp carries NB=8 batch elements. Gates computed pairwise with fma.f32x2:
// (i,f) and (g,o) accumulators per batch; weights come as aligned reg pairs
// straight out of one LDS.128; h comes as duplicated quads via broadcast
// LDS.128 from a double-buffered smem stage (no shuffles in the hot loop).
// ---------------------------------------------------------------------------
__global__ void __launch_bounds__(32) scan_kernel(
    const float* __restrict__ x,
    const float* __restrict__ h0,  const float* __restrict__ c0,
    const float* __restrict__ Wih1,
    const float* __restrict__ bih1, const float* __restrict__ bhh1)
{
    __shared__ float4 Ws[32 * 32];          // 16 KB: [k][j] packed gate weights
    __shared__ float4 Hs[2][NB / 2][32];    // 4 KB: [buf][pairgrp][k] = (h2g,h2g,h2g1,h2g1)

    const int j  = threadIdx.x;             // lane = hidden unit
    const int b0 = blockIdx.x * NB;

    #pragma unroll
    for (int i = 0; i < 32; i++)
        Ws[i * 32 + j] = g_W1p[i * 32 + j];

    // Per-lane constants: combined bias and input weight, gate-paired
    const u64 biasIF = pack2(bih1[0  + j] + bhh1[0  + j], bih1[32 + j] + bhh1[32 + j]);
    const u64 biasGO = pack2(bih1[64 + j] + bhh1[64 + j], bih1[96 + j] + bhh1[96 + j]);
    const u64 wihIF  = pack2(Wih1[0  + j], Wih1[32 + j]);
    const u64 wihGO  = pack2(Wih1[64 + j], Wih1[96 + j]);

    // Carry c in registers; h lives in the smem stage
    float c[NB];
    #pragma unroll
    for (int b = 0; b < NB; b++) c[b] = c0[(b0 + b) * HID + j];

    #pragma unroll
    for (int g = 0; g < NB / 2; g++) {
        float ha = h0[(b0 + 2 * g)     * HID + j];
        float hb = h0[(b0 + 2 * g + 1) * HID + j];
        Hs[0][g][j] = make_float4(ha, ha, hb, hb);
    }

    // lane b (<NB) holds x[t][b0+b]; prefetch one step ahead
    float xc = (j < NB) ? x[b0 + j] : 0.0f;
    __syncwarp();

    #pragma unroll 1
    for (int t = 0; t < SEQ; t++) {
        const int rb = t & 1;

        float xn = 0.0f;
        if (j < NB && t + 1 < SEQ) xn = x[(t + 1) * BATCH + b0 + j];

        u64 aIF[NB], aGO[NB];
        #pragma unroll
        for (int b = 0; b < NB; b++) {
            float xb = __shfl_sync(0xffffffffu, xc, b);
            u64 xd = pack2(xb, xb);
            aIF[b] = fma2(xd, wihIF, biasIF);
            aGO[b] = fma2(xd, wihGO, biasGO);
        }

        // recurrent matvec: per k, 1 LDS.128 (weights, per-lane) +
        // NB/2 broadcast LDS.128 (duplicated h pairs) + 16 FFMA2
        #pragma unroll
        for (int k = 0; k < 32; k++) {
            float4 w = Ws[k * 32 + j];
            u64 wIF = pack2(w.x, w.y);
            u64 wGO = pack2(w.z, w.w);
            #pragma unroll
            for (int g = 0; g < NB / 2; g++) {
                float4 hq = Hs[rb][g][k];       // broadcast
                u64 hA = pack2(hq.x, hq.y);     // (h[2g],   h[2g])
                u64 hB = pack2(hq.z, hq.w);     // (h[2g+1], h[2g+1])
                aIF[2 * g]     = fma2(hA, wIF, aIF[2 * g]);
                aGO[2 * g]     = fma2(hA, wGO, aGO[2 * g]);
                aIF[2 * g + 1] = fma2(hB, wIF, aIF[2 * g + 1]);
                aGO[2 * g + 1] = fma2(hB, wGO, aGO[2 * g + 1]);
            }
        }

        float hn[NB];
        #pragma unroll
        for (int b = 0; b < NB; b++) {
            float ai, af, ag, ao;
            unpack2(aIF[b], ai, af);
            unpack2(aGO[b], ag, ao);
            float ig = sigf(ai);
            float fg = sigf(af);
            float gg = tanhf_fast(ag);
            float og = sigf(ao);
            c[b]  = fmaf(fg, c[b], ig * gg);
            hn[b] = og * tanhf_fast(c[b]);
        }

        #pragma unroll
        for (int g = 0; g < NB / 2; g++)
            Hs[rb ^ 1][g][j] = make_float4(hn[2 * g], hn[2 * g],
                                           hn[2 * g + 1], hn[2 * g + 1]);
        xc = xn;
        __syncwarp();
    }

    // SEQ even -> final h landed in buffer 0. Write [j][b] for the tail.
    #pragma unroll
    for (int b = 0; b < NB; b++) {
        float4 hq = Hs[0][b >> 1][j];
        float hv = (b & 1) ? hq.z : hq.x;
        g_hf[j * BATCH + b0 + b] = hv;
        g_cf[j * BATCH + b0 + b] = c[b];
    }
}

// ---------------------------------------------------------------------------
// Kernel 2: cell 2 (input = hidden = hf, cell = cf) + FC. One thread per batch.
// Wih2 + Whh2 folded into a single [128,32] matrix.
// ---------------------------------------------------------------------------
__global__ void __launch_bounds__(128) tail_kernel(
    const float* __restrict__ Wih2, const float* __restrict__ Whh2,
    const float* __restrict__ bih2, const float* __restrict__ bhh2,
    const float* __restrict__ Wfc,  const float* __restrict__ bfc,
    float* __restrict__ out)
{
    __shared__ float W2s[128 * 32];
    __shared__ float b2s[128];
    __shared__ float wfcs[32];
    const int tid = threadIdx.x;

    for (int i = tid; i < 128 * 32; i += 128) W2s[i] = Wih2[i] + Whh2[i];
    if (tid < 128) b2s[tid] = bih2[tid] + bhh2[tid];
    if (tid < 32)  wfcs[tid] = Wfc[tid];
    __syncthreads();

    const int b = blockIdx.x * 128 + tid;

    float h[HID];
    #pragma unroll
    for (int k = 0; k < HID; k++) h[k] = g_hf[k * BATCH + b];   // coalesced

    float acc_out = bfc[0];
    #pragma unroll
    for (int jj = 0; jj < HID; jj++) {
        float ai = b2s[0  + jj];
        float af = b2s[32 + jj];
        float ag = b2s[64 + jj];
        float ao = b2s[96 + jj];
        #pragma unroll
        for (int k = 0; k < HID; k++) {
            float hk = h[k];
            ai = fmaf(hk, W2s[(0  + jj) * HID + k], ai);
            af = fmaf(hk, W2s[(32 + jj) * HID + k], af);
            ag = fmaf(hk, W2s[(64 + jj) * HID + k], ag);
            ao = fmaf(hk, W2s[(96 + jj) * HID + k], ao);
        }
        float cf = g_cf[jj * BATCH + b];
        float cn = fmaf(sigf(af), cf, sigf(ai) * tanhf_fast(ag));
        float hn = sigf(ao) * tanhf_fast(cn);
        acc_out = fmaf(hn, wfcs[jj], acc_out);
    }
    out[b] = acc_out;
}

// ---------------------------------------------------------------------------
// kernel_launch: pack -> scan -> tail (default stream, graph-capturable)
// Input order: x,h0,c0,h1,c1,Wih1,Whh1,bih1,bhh1,Wih2,Whh2,bih2,bhh2,Wfc,bfc
// ---------------------------------------------------------------------------
extern "C" void kernel_launch(void* const* d_in, const int* in_sizes, int n_in,
                              void* d_out, int out_size)
{
    const float* x    = (const float*)d_in[0];
    const float* h0   = (const float*)d_in[1];
    const float* c0   = (const float*)d_in[2];
    const float* Wih1 = (const float*)d_in[5];
    const float* Whh1 = (const float*)d_in[6];
    const float* bih1 = (const float*)d_in[7];
    const float* bhh1 = (const float*)d_in[8];
    const float* Wih2 = (const float*)d_in[9];
    const float* Whh2 = (const float*)d_in[10];
    const float* bih2 = (const float*)d_in[11];
    const float* bhh2 = (const float*)d_in[12];
    const float* Wfc  = (const float*)d_in[13];
    const float* bfc  = (const float*)d_in[14];
    float* out = (float*)d_out;

    pack_kernel<<<8, 128>>>(Whh1);
    scan_kernel<<<BATCH / NB, 32>>>(x, h0, c0, Wih1, bih1, bhh1);
    tail_kernel<<<BATCH / 128, 128>>>(Wih2, Whh2, bih2, bhh2, Wfc, bfc, out);
}

// round 3
// speedup vs baseline: 1.1864x; 1.1536x over previous
#include <cuda_runtime.h>
#include <cuda_bf16.h>

// Problem constants
#define BATCH 4096
#define SEQ   512
#define HID   32
#define NB    4            // batch elements per warp -> 1024 one-warp blocks
#define KREG  20           // k-slices of Whh kept in registers (rest via smem)

// Scratch (device globals are the allowed scratch mechanism)
__device__ float4 g_W1p[32 * 32];         // packed Whh1: [k][j] -> (Wi,Wf,Wg,Wo)
__device__ float  g_hf[HID * BATCH];      // final h of cell1, layout [j][b]
__device__ float  g_cf[HID * BATCH];      // final c of cell1, layout [j][b]

using u64 = unsigned long long;

// ---- packed f32x2 helpers (FFMA2 path, PTX-only) ----
__device__ __forceinline__ u64 pack2(float lo, float hi) {
    u64 r; asm("mov.b64 %0, {%1, %2};" : "=l"(r) : "f"(lo), "f"(hi)); return r;
}
__device__ __forceinline__ void unpack2(u64 v, float& lo, float& hi) {
    asm("mov.b64 {%0, %1}, %2;" : "=f"(lo), "=f"(hi) : "l"(v));
}
__device__ __forceinline__ u64 fma2(u64 a, u64 b, u64 c) {
    u64 d; asm("fma.rn.f32x2 %0, %1, %2, %3;" : "=l"(d) : "l"(a), "l"(b), "l"(c)); return d;
}

// ---- fast, accurate activations (MUFU EX2 + RCP; ~1e-6 abs err) ----
__device__ __forceinline__ float sigf(float v) {
    return __fdividef(1.0f, 1.0f + __expf(-v));
}
__device__ __forceinline__ float tanhf_fast(float v) {
    return __fdividef(2.0f, 1.0f + __expf(-2.0f * v)) - 1.0f;
}

// ---------------------------------------------------------------------------
// Kernel 0: pack Whh1 [128,32] row-major into [k][j] float4 (i,f,g,o) layout
// ---------------------------------------------------------------------------
__global__ void pack_kernel(const float* __restrict__ Whh1) {
    int idx = blockIdx.x * blockDim.x + threadIdx.x;   // 0..1023
    if (idx < 1024) {
        int k = idx >> 5;
        int j = idx & 31;
        float4 w;
        w.x = Whh1[(0  + j) * HID + k];   // i gate
        w.y = Whh1[(32 + j) * HID + k];   // f gate
        w.z = Whh1[(64 + j) * HID + k];   // g gate
        w.w = Whh1[(96 + j) * HID + k];   // o gate
        g_W1p[idx] = w;                   // idx = k*32 + j
    }
}

// ---------------------------------------------------------------------------
// Kernel 1: sequential scan. 1 warp/block, lane = hidden unit j, NB=4 batch
// elements per warp. Gate pairs (i,f) and (g,o) accumulate via fma.rn.f32x2.
// Weights: KREG k-slices in registers, rest one LDS.128 per k. h: duplicated
// pairs in smem, read as broadcast ld.shared.v2.u64 -> operands feed FFMA2
// with zero repack instructions in the hot loop.
// ---------------------------------------------------------------------------
__global__ void __launch_bounds__(32) scan_kernel(
    const float* __restrict__ x,
    const float* __restrict__ h0,  const float* __restrict__ c0,
    const float* __restrict__ Wih1,
    const float* __restrict__ bih1, const float* __restrict__ bhh1)
{
    __shared__ ulonglong2 Ws2[(32 - KREG) * 32];   // [(k-KREG)][j] = (wIF, wGO)
    __shared__ ulonglong2 Hs[2][NB / 2][32];       // [buf][pair][k] = ((h2g,h2g),(h2g+1,h2g+1))

    const int j  = threadIdx.x;           // lane = hidden unit
    const int b0 = blockIdx.x * NB;

    // Weight registers for k = 0..KREG-1 (4 regs per k)
    u64 wIFr[KREG], wGOr[KREG];
    #pragma unroll
    for (int k = 0; k < KREG; k++) {
        float4 w = g_W1p[k * 32 + j];
        wIFr[k] = pack2(w.x, w.y);
        wGOr[k] = pack2(w.z, w.w);
    }
    // Remaining k-slices staged to smem as ready-to-use u64 pairs
    #pragma unroll
    for (int k = KREG; k < 32; k++) {
        float4 w = g_W1p[k * 32 + j];
        ulonglong2 ww;
        ww.x = pack2(w.x, w.y);
        ww.y = pack2(w.z, w.w);
        Ws2[(k - KREG) * 32 + j] = ww;
    }

    // Per-lane constants: combined bias and input weight, gate-paired
    const u64 biasIF = pack2(bih1[0  + j] + bhh1[0  + j], bih1[32 + j] + bhh1[32 + j]);
    const u64 biasGO = pack2(bih1[64 + j] + bhh1[64 + j], bih1[96 + j] + bhh1[96 + j]);
    const u64 wihIF  = pack2(Wih1[0  + j], Wih1[32 + j]);
    const u64 wihGO  = pack2(Wih1[64 + j], Wih1[96 + j]);

    // Carry c in registers; h lives in the smem stage
    float c[NB];
    #pragma unroll
    for (int b = 0; b < NB; b++) c[b] = c0[(b0 + b) * HID + j];

    #pragma unroll
    for (int g = 0; g < NB / 2; g++) {
        float ha = h0[(b0 + 2 * g)     * HID + j];
        float hb = h0[(b0 + 2 * g + 1) * HID + j];
        ulonglong2 hq;
        hq.x = pack2(ha, ha);
        hq.y = pack2(hb, hb);
        Hs[0][g][j] = hq;
    }

    // lane b (<NB) holds x[t][b0+b]; prefetch one step ahead
    float xc = (j < NB) ? x[b0 + j] : 0.0f;
    __syncwarp();

    #pragma unroll 1
    for (int t = 0; t < SEQ; t++) {
        const int rb = t & 1;

        float xn = 0.0f;
        if (j < NB && t + 1 < SEQ) xn = x[(t + 1) * BATCH + b0 + j];

        u64 aIF[NB], aGO[NB];
        #pragma unroll
        for (int b = 0; b < NB; b++) {
            float xb = __shfl_sync(0xffffffffu, xc, b);
            u64 xd = pack2(xb, xb);
            aIF[b] = fma2(xd, wihIF, biasIF);
            aGO[b] = fma2(xd, wihGO, biasGO);
        }

        // recurrent matvec: per k, 2 broadcast LDS.128 (h pairs) + 8 FFMA2;
        // weights from registers for k<KREG, else 1 lane-distinct LDS.128.
        #pragma unroll
        for (int k = 0; k < 32; k++) {
            u64 wIF, wGO;
            if (k < KREG) {
                wIF = wIFr[k];
                wGO = wGOr[k];
            } else {
                ulonglong2 ww = Ws2[(k - KREG) * 32 + j];
                wIF = ww.x;
                wGO = ww.y;
            }
            #pragma unroll
            for (int g = 0; g < NB / 2; g++) {
                ulonglong2 hq = Hs[rb][g][k];     // broadcast, pre-paired
                aIF[2 * g]     = fma2(hq.x, wIF, aIF[2 * g]);
                aGO[2 * g]     = fma2(hq.x, wGO, aGO[2 * g]);
                aIF[2 * g + 1] = fma2(hq.y, wIF, aIF[2 * g + 1]);
                aGO[2 * g + 1] = fma2(hq.y, wGO, aGO[2 * g + 1]);
            }
        }

        float hn[NB];
        #pragma unroll
        for (int b = 0; b < NB; b++) {
            float ai, af, ag, ao;
            unpack2(aIF[b], ai, af);
            unpack2(aGO[b], ag, ao);
            float ig = sigf(ai);
            float fg = sigf(af);
            float gg = tanhf_fast(ag);
            float og = sigf(ao);
            c[b]  = fmaf(fg, c[b], ig * gg);
            hn[b] = og * tanhf_fast(c[b]);
        }

        #pragma unroll
        for (int g = 0; g < NB / 2; g++) {
            ulonglong2 hq;
            hq.x = pack2(hn[2 * g],     hn[2 * g]);
            hq.y = pack2(hn[2 * g + 1], hn[2 * g + 1]);
            Hs[rb ^ 1][g][j] = hq;
        }
        xc = xn;
        __syncwarp();
    }

    // SEQ even -> final h landed in buffer 0. Write [j][b] for the tail.
    #pragma unroll
    for (int b = 0; b < NB; b++) {
        ulonglong2 hq = Hs[0][b >> 1][j];
        float lo, hi;
        unpack2((b & 1) ? hq.y : hq.x, lo, hi);
        g_hf[j * BATCH + b0 + b] = lo;
        g_cf[j * BATCH + b0 + b] = c[b];
    }
}

// ---------------------------------------------------------------------------
// Kernel 2: cell 2 (input = hidden = hf, cell = cf) + FC. One thread per batch.
// Wih2 + Whh2 folded into a single [128,32] matrix.
// ---------------------------------------------------------------------------
__global__ void __launch_bounds__(128) tail_kernel(
    const float* __restrict__ Wih2, const float* __restrict__ Whh2,
    const float* __restrict__ bih2, const float* __restrict__ bhh2,
    const float* __restrict__ Wfc,  const float* __restrict__ bfc,
    float* __restrict__ out)
{
    __shared__ float W2s[128 * 32];
    __shared__ float b2s[128];
    __shared__ float wfcs[32];
    const int tid = threadIdx.x;

    for (int i = tid; i < 128 * 32; i += 128) W2s[i] = Wih2[i] + Whh2[i];
    if (tid < 128) b2s[tid] = bih2[tid] + bhh2[tid];
    if (tid < 32)  wfcs[tid] = Wfc[tid];
    __syncthreads();

    const int b = blockIdx.x * 128 + tid;

    float h[HID];
    #pragma unroll
    for (int k = 0; k < HID; k++) h[k] = g_hf[k * BATCH + b];   // coalesced

    float acc_out = bfc[0];
    #pragma unroll
    for (int jj = 0; jj < HID; jj++) {
        float ai = b2s[0  + jj];
        float af = b2s[32 + jj];
        float ag = b2s[64 + jj];
        float ao = b2s[96 + jj];
        #pragma unroll
        for (int k = 0; k < HID; k++) {
            float hk = h[k];
            ai = fmaf(hk, W2s[(0  + jj) * HID + k], ai);
            af = fmaf(hk, W2s[(32 + jj) * HID + k], af);
            ag = fmaf(hk, W2s[(64 + jj) * HID + k], ag);
            ao = fmaf(hk, W2s[(96 + jj) * HID + k], ao);
        }
        float cf = g_cf[jj * BATCH + b];
        float cn = fmaf(sigf(af), cf, sigf(ai) * tanhf_fast(ag));
        float hn = sigf(ao) * tanhf_fast(cn);
        acc_out = fmaf(hn, wfcs[jj], acc_out);
    }
    out[b] = acc_out;
}

// ---------------------------------------------------------------------------
// kernel_launch: pack -> scan -> tail (default stream, graph-capturable)
// Input order: x,h0,c0,h1,c1,Wih1,Whh1,bih1,bhh1,Wih2,Whh2,bih2,bhh2,Wfc,bfc
// ---------------------------------------------------------------------------
extern "C" void kernel_launch(void* const* d_in, const int* in_sizes, int n_in,
                              void* d_out, int out_size)
{
    const float* x    = (const float*)d_in[0];
    const float* h0   = (const float*)d_in[1];
    const float* c0   = (const float*)d_in[2];
    const float* Wih1 = (const float*)d_in[5];
    const float* Whh1 = (const float*)d_in[6];
    const float* bih1 = (const float*)d_in[7];
    const float* bhh1 = (const float*)d_in[8];
    const float* Wih2 = (const float*)d_in[9];
    const float* Whh2 = (const float*)d_in[10];
    const float* bih2 = (const float*)d_in[11];
    const float* bhh2 = (const float*)d_in[12];
    const float* Wfc  = (const float*)d_in[13];
    const float* bfc  = (const float*)d_in[14];
    float* out = (float*)d_out;

    pack_kernel<<<8, 128>>>(Whh1);
    scan_kernel<<<BATCH / NB, 32>>>(x, h0, c0, Wih1, bih1, bhh1);
    tail_kernel<<<BATCH / 128, 128>>>(Wih2, Whh2, bih2, bhh2, Wfc, bfc, out);
}